// round 6
// baseline (speedup 1.0000x reference)
#include <cuda_runtime.h>
#include <cuda_fp16.h>

#define BB 4
#define NN 512
#define MM 512
#define LD 512
#define AG 256
#define ROWS (BB * NN)   // 2048

// Projections stored as fp16 (rounding happens here either way; dist reads half).
__device__ __half g_dl[ROWS * AG];   // [row][a]
__device__ __half g_cl[ROWS * AG];   // [row][a]

__device__ __forceinline__ unsigned tanh_h2(unsigned x) {
    unsigned y;
    asm("tanh.approx.f16x2 %0, %1;" : "=r"(y) : "r"(x));
    return y;
}
__device__ __forceinline__ unsigned hadd2_raw(unsigned a, unsigned b) {
    unsigned r;
    asm("add.f16x2 %0, %1, %2;" : "=r"(r) : "r"(a), "r"(b));
    return r;
}
__device__ __forceinline__ __half2 u2h2(unsigned v) {
    __half2 h;
    *(unsigned*)&h = v;
    return h;
}

// ---------------------------------------------------------------------------
// Projection GEMM: out[row][a] = in[row][:] @ W + bias  (fp32 math, fp16 store)
// BM=64, BN=64, BK=16, 256 threads, 4x4/thread, double-buffered smem.
// ---------------------------------------------------------------------------
__global__ __launch_bounds__(256) void proj_kernel(
    const float* __restrict__ data, const float* __restrict__ crit,
    const float* __restrict__ Wl, const float* __restrict__ bl,
    const float* __restrict__ Wr, const float* __restrict__ br)
{
    __shared__ float As[2][16][68];
    __shared__ float Bs[2][16][68];

    const float* A; const float* W; const float* bias; __half* out;
    if (blockIdx.z == 0) { A = data; W = Wl; bias = bl; out = g_dl; }
    else                 { A = crit; W = Wr; bias = br; out = g_cl; }
    const int row0 = blockIdx.x * 64;
    const int col0 = blockIdx.y * 64;

    const int tid = threadIdx.x;
    const int ar  = tid >> 2;
    const int ac  = (tid & 3) << 2;
    const int bro = tid >> 4;
    const int bco = (tid & 15) << 2;
    const int ty  = tid >> 4;
    const int tx  = tid & 15;

    const float* Aptr = A + (row0 + ar) * LD + ac;
    const float* Wptr = W + bro * AG + col0 + bco;

    float acc[4][4];
#pragma unroll
    for (int i = 0; i < 4; i++)
#pragma unroll
        for (int j = 0; j < 4; j++) acc[i][j] = 0.f;

    {
        float4 av = *(const float4*)(Aptr);
        float4 bv = *(const float4*)(Wptr);
        As[0][ac + 0][ar] = av.x;
        As[0][ac + 1][ar] = av.y;
        As[0][ac + 2][ar] = av.z;
        As[0][ac + 3][ar] = av.w;
        *(float4*)&Bs[0][bro][bco] = bv;
    }
    __syncthreads();

    int cur = 0;
    for (int k0 = 0; k0 < LD; k0 += 16) {
        float4 an, bn;
        const bool more = (k0 + 16) < LD;
        if (more) {
            an = *(const float4*)(Aptr + k0 + 16);
            bn = *(const float4*)(Wptr + (size_t)(k0 + 16) * AG);
        }
#pragma unroll
        for (int k = 0; k < 16; k++) {
            float a[4], b[4];
            *(float4*)a = *(const float4*)&As[cur][k][ty << 2];
            *(float4*)b = *(const float4*)&Bs[cur][k][tx << 2];
#pragma unroll
            for (int i = 0; i < 4; i++)
#pragma unroll
                for (int j = 0; j < 4; j++)
                    acc[i][j] = fmaf(a[i], b[j], acc[i][j]);
        }
        if (more) {
            int nxt = cur ^ 1;
            As[nxt][ac + 0][ar] = an.x;
            As[nxt][ac + 1][ar] = an.y;
            As[nxt][ac + 2][ar] = an.z;
            As[nxt][ac + 3][ar] = an.w;
            *(float4*)&Bs[nxt][bro][bco] = bn;
            __syncthreads();
            cur = nxt;
        }
    }

#pragma unroll
    for (int i = 0; i < 4; i++) {
        int row = row0 + (ty << 2) + i;
        int c   = col0 + (tx << 2);
        __half2 h01 = __floats2half2_rn(acc[i][0] + bias[c + 0],
                                        acc[i][1] + bias[c + 1]);
        __half2 h23 = __floats2half2_rn(acc[i][2] + bias[c + 2],
                                        acc[i][3] + bias[c + 3]);
        uint2 pk;
        pk.x = *(unsigned*)&h01;
        pk.y = *(unsigned*)&h23;
        *(uint2*)(out + (size_t)row * AG + c) = pk;   // STG.64
    }
}

// ---------------------------------------------------------------------------
// Distance kernel: dists[b,n,m] = sum_a tanh(dl+cl)*agg
// 32x32 tile, 256 threads, 2x2/thread.  ALL 256 a staged once (fp16, a-major,
// row stride 34 halves) -> exactly ONE __syncthreads, sync-free main loop.
// smem ~36KB -> 4 blocks/SM = 32 warps (100% occ) for latency hiding.
// ---------------------------------------------------------------------------
__global__ __launch_bounds__(256, 4) void dist_kernel(
    const float* __restrict__ agg, float* __restrict__ out)
{
    __shared__ __align__(16) float aggs[AG];
    __shared__ __half dls[AG][34];   // [a][n], pad 34 (68B rows, 4B aligned)
    __shared__ __half cls[AG][34];   // [a][m]

    const int b   = blockIdx.z;
    const int n0  = blockIdx.x << 5;
    const int m0  = blockIdx.y << 5;
    const int tid = threadIdx.x;
    const int ty2 = (tid >> 4) << 1;   // n rows ty2, ty2+1
    const int tx2 = (tid & 15) << 1;   // m cols tx2, tx2+1

    aggs[tid] = agg[tid];

    const __half* dlb = g_dl + (size_t)(b * NN + n0) * AG;
    const __half* clb = g_cl + (size_t)(b * MM + m0) * AG;

    // Stage full 32 rows x 256 a of both arrays, transposing to a-major.
    // Per warp: fixed a-chunk of 8, rows = lanes -> coalesced 16B GMEM loads.
#pragma unroll
    for (int h = 0; h < 4; h++) {
        int idx = tid + (h << 8);          // 0..1023
        int r   = idx & 31;                // row 0..31
        int a8  = (idx >> 5) << 3;         // a chunk 0,8,...,248
        uint4 v = *(const uint4*)(dlb + (size_t)r * AG + a8);
        const __half2* vh = (const __half2*)&v;
#pragma unroll
        for (int i = 0; i < 4; i++) {
            dls[a8 + 2 * i + 0][r] = __low2half(vh[i]);
            dls[a8 + 2 * i + 1][r] = __high2half(vh[i]);
        }
        uint4 w = *(const uint4*)(clb + (size_t)r * AG + a8);
        const __half2* wh = (const __half2*)&w;
#pragma unroll
        for (int i = 0; i < 4; i++) {
            cls[a8 + 2 * i + 0][r] = __low2half(wh[i]);
            cls[a8 + 2 * i + 1][r] = __high2half(wh[i]);
        }
    }
    __syncthreads();

    float a00 = 0.f, a01 = 0.f, a10 = 0.f, a11 = 0.f;

#define DSTEP(aa, g) {                                              \
        unsigned dpair = *(const unsigned*)&dls[aa][ty2];           \
        unsigned cpair = *(const unsigned*)&cls[aa][tx2];           \
        unsigned d00 = __byte_perm(dpair, 0, 0x1010);               \
        unsigned d11 = __byte_perm(dpair, 0, 0x3232);               \
        __half2 t0 = u2h2(tanh_h2(hadd2_raw(d00, cpair)));          \
        __half2 t1 = u2h2(tanh_h2(hadd2_raw(d11, cpair)));          \
        a00 = fmaf(__low2float(t0),  (g), a00);                     \
        a01 = fmaf(__high2float(t0), (g), a01);                     \
        a10 = fmaf(__low2float(t1),  (g), a10);                     \
        a11 = fmaf(__high2float(t1), (g), a11); }

#pragma unroll 4
    for (int a = 0; a < AG; a += 4) {
        float4 g4 = *(const float4*)&aggs[a];
        DSTEP(a + 0, g4.x);
        DSTEP(a + 1, g4.y);
        DSTEP(a + 2, g4.z);
        DSTEP(a + 3, g4.w);
    }
#undef DSTEP

    float* o = out + ((size_t)(b * NN + n0 + ty2) << 9) + m0 + tx2;
    *(float2*)o        = make_float2(a00, a01);
    *(float2*)(o + MM) = make_float2(a10, a11);
}

extern "C" void kernel_launch(void* const* d_in, const int* in_sizes, int n_in,
                              void* d_out, int out_size) {
    const float* data = (const float*)d_in[0];
    const float* crit = (const float*)d_in[1];
    const float* Wl   = (const float*)d_in[2];
    const float* bl   = (const float*)d_in[3];
    const float* Wr   = (const float*)d_in[4];
    const float* br   = (const float*)d_in[5];
    const float* agg  = (const float*)d_in[6];
    float* out = (float*)d_out;

    proj_kernel<<<dim3(32, 4, 2), 256>>>(data, crit, Wl, bl, Wr, br);
    dist_kernel<<<dim3(16, 16, 4), 256>>>(agg, out);
}

// round 7
// speedup vs baseline: 1.0100x; 1.0100x over previous
#include <cuda_runtime.h>
#include <cuda_fp16.h>

#define BB 4
#define NN 512
#define MM 512
#define LD 512
#define AG 256
#define ROWS (BB * NN)   // 2048

// Projections stored as fp16 (rounding happens here either way; dist reads half).
__device__ __half g_dl[ROWS * AG];   // [row][a]
__device__ __half g_cl[ROWS * AG];   // [row][a]

__device__ __forceinline__ unsigned tanh_h2(unsigned x) {
    unsigned y;
    asm("tanh.approx.f16x2 %0, %1;" : "=r"(y) : "r"(x));
    return y;
}
__device__ __forceinline__ unsigned hadd2_raw(unsigned a, unsigned b) {
    unsigned r;
    asm("add.f16x2 %0, %1, %2;" : "=r"(r) : "r"(a), "r"(b));
    return r;
}
__device__ __forceinline__ __half2 u2h2(unsigned v) {
    __half2 h;
    *(unsigned*)&h = v;
    return h;
}

// ---------------------------------------------------------------------------
// Projection GEMM: out[row][a] = in[row][:] @ W + bias  (fp32 math, fp16 store)
// BM=64, BN=64, BK=16, 256 threads, 4x4/thread, double-buffered smem.
// Measured ~93% of the SIMT FFMA roofline — unchanged.
// ---------------------------------------------------------------------------
__global__ __launch_bounds__(256) void proj_kernel(
    const float* __restrict__ data, const float* __restrict__ crit,
    const float* __restrict__ Wl, const float* __restrict__ bl,
    const float* __restrict__ Wr, const float* __restrict__ br)
{
    __shared__ float As[2][16][68];
    __shared__ float Bs[2][16][68];

    const float* A; const float* W; const float* bias; __half* out;
    if (blockIdx.z == 0) { A = data; W = Wl; bias = bl; out = g_dl; }
    else                 { A = crit; W = Wr; bias = br; out = g_cl; }
    const int row0 = blockIdx.x * 64;
    const int col0 = blockIdx.y * 64;

    const int tid = threadIdx.x;
    const int ar  = tid >> 2;
    const int ac  = (tid & 3) << 2;
    const int bro = tid >> 4;
    const int bco = (tid & 15) << 2;
    const int ty  = tid >> 4;
    const int tx  = tid & 15;

    const float* Aptr = A + (row0 + ar) * LD + ac;
    const float* Wptr = W + bro * AG + col0 + bco;

    float acc[4][4];
#pragma unroll
    for (int i = 0; i < 4; i++)
#pragma unroll
        for (int j = 0; j < 4; j++) acc[i][j] = 0.f;

    {
        float4 av = *(const float4*)(Aptr);
        float4 bv = *(const float4*)(Wptr);
        As[0][ac + 0][ar] = av.x;
        As[0][ac + 1][ar] = av.y;
        As[0][ac + 2][ar] = av.z;
        As[0][ac + 3][ar] = av.w;
        *(float4*)&Bs[0][bro][bco] = bv;
    }
    __syncthreads();

    int cur = 0;
    for (int k0 = 0; k0 < LD; k0 += 16) {
        float4 an, bn;
        const bool more = (k0 + 16) < LD;
        if (more) {
            an = *(const float4*)(Aptr + k0 + 16);
            bn = *(const float4*)(Wptr + (size_t)(k0 + 16) * AG);
        }
#pragma unroll
        for (int k = 0; k < 16; k++) {
            float a[4], b[4];
            *(float4*)a = *(const float4*)&As[cur][k][ty << 2];
            *(float4*)b = *(const float4*)&Bs[cur][k][tx << 2];
#pragma unroll
            for (int i = 0; i < 4; i++)
#pragma unroll
                for (int j = 0; j < 4; j++)
                    acc[i][j] = fmaf(a[i], b[j], acc[i][j]);
        }
        if (more) {
            int nxt = cur ^ 1;
            As[nxt][ac + 0][ar] = an.x;
            As[nxt][ac + 1][ar] = an.y;
            As[nxt][ac + 2][ar] = an.z;
            As[nxt][ac + 3][ar] = an.w;
            *(float4*)&Bs[nxt][bro][bco] = bn;
            __syncthreads();
            cur = nxt;
        }
    }

#pragma unroll
    for (int i = 0; i < 4; i++) {
        int row = row0 + (ty << 2) + i;
        int c   = col0 + (tx << 2);
        __half2 h01 = __floats2half2_rn(acc[i][0] + bias[c + 0],
                                        acc[i][1] + bias[c + 1]);
        __half2 h23 = __floats2half2_rn(acc[i][2] + bias[c + 2],
                                        acc[i][3] + bias[c + 3]);
        uint2 pk;
        pk.x = *(unsigned*)&h01;
        pk.y = *(unsigned*)&h23;
        *(uint2*)(out + (size_t)row * AG + c) = pk;   // STG.64
    }
}

// ---------------------------------------------------------------------------
// Distance kernel: dists[b,n,m] = sum_a tanh(dl+cl)*agg
// 32x32 tile, 128 threads, 2(n) x 4(m) per thread -> 8 terms per a-step:
//   1 LDS.32(d) + 2 PRMT + 1 LDS.64(c) + 4 HADD2 + 4 MUFU.H2 + 8 F2F + 8 FFMA
// MUFU floor ~31us; issue floor ~28us. a chunked 128 -> smem ~19KB,
// __launch_bounds__(128,8): 8 blocks/SM, grid 1024 fully co-resident (no tail).
// ---------------------------------------------------------------------------
__global__ __launch_bounds__(128, 8) void dist_kernel(
    const float* __restrict__ agg, float* __restrict__ out)
{
    __shared__ __align__(16) float aggs[AG];
    __shared__ __half dls[128][34];   // [a][n]  (LDS.32 -> 4B align ok)
    __shared__ __half cls[128][36];   // [a][m]  stride 36 halves = 72B (8B align)

    const int b   = blockIdx.z;
    const int n0  = blockIdx.x << 5;
    const int m0  = blockIdx.y << 5;
    const int tid = threadIdx.x;
    const int ty2 = (tid >> 3) << 1;   // n rows ty2, ty2+1   (0..30)
    const int tx4 = (tid & 7) << 2;    // m cols tx4..tx4+3   (0..28)

    aggs[tid]       = agg[tid];
    aggs[tid + 128] = agg[tid + 128];

    const __half* dlb = g_dl + (size_t)(b * NN + n0) * AG;
    const __half* clb = g_cl + (size_t)(b * MM + m0) * AG;

    float a00 = 0.f, a01 = 0.f, a02 = 0.f, a03 = 0.f;
    float a10 = 0.f, a11 = 0.f, a12 = 0.f, a13 = 0.f;

    for (int c0 = 0; c0 < AG; c0 += 128) {
        __syncthreads();   // protect previous chunk (covers aggs on iter 0)
        // stage 32 rows x 128 a of both arrays, transposed to a-major
#pragma unroll
        for (int h = 0; h < 4; h++) {
            int idx = tid + (h << 7);        // 0..511
            int r   = idx & 31;              // row 0..31
            int a8  = (idx >> 5) << 3;       // a 0,8,...,120
            uint4 v = *(const uint4*)(dlb + (size_t)r * AG + c0 + a8);
            const __half2* vh = (const __half2*)&v;
#pragma unroll
            for (int i = 0; i < 4; i++) {
                dls[a8 + 2 * i + 0][r] = __low2half(vh[i]);
                dls[a8 + 2 * i + 1][r] = __high2half(vh[i]);
            }
            uint4 w = *(const uint4*)(clb + (size_t)r * AG + c0 + a8);
            const __half2* wh = (const __half2*)&w;
#pragma unroll
            for (int i = 0; i < 4; i++) {
                cls[a8 + 2 * i + 0][r] = __low2half(wh[i]);
                cls[a8 + 2 * i + 1][r] = __high2half(wh[i]);
            }
        }
        __syncthreads();

#define DSTEP(aa, g) {                                              \
        unsigned dpair = *(const unsigned*)&dls[aa][ty2];           \
        uint2    cq    = *(const uint2*)&cls[aa][tx4];              \
        unsigned d00 = __byte_perm(dpair, 0, 0x1010);               \
        unsigned d11 = __byte_perm(dpair, 0, 0x3232);               \
        __half2 t00 = u2h2(tanh_h2(hadd2_raw(d00, cq.x)));          \
        __half2 t01 = u2h2(tanh_h2(hadd2_raw(d00, cq.y)));          \
        __half2 t10 = u2h2(tanh_h2(hadd2_raw(d11, cq.x)));          \
        __half2 t11 = u2h2(tanh_h2(hadd2_raw(d11, cq.y)));          \
        a00 = fmaf(__low2float(t00),  (g), a00);                    \
        a01 = fmaf(__high2float(t00), (g), a01);                    \
        a02 = fmaf(__low2float(t01),  (g), a02);                    \
        a03 = fmaf(__high2float(t01), (g), a03);                    \
        a10 = fmaf(__low2float(t10),  (g), a10);                    \
        a11 = fmaf(__high2float(t10), (g), a11);                    \
        a12 = fmaf(__low2float(t11),  (g), a12);                    \
        a13 = fmaf(__high2float(t11), (g), a13); }

#pragma unroll 4
        for (int aa = 0; aa < 128; aa += 4) {
            float4 g4 = *(const float4*)&aggs[c0 + aa];
            DSTEP(aa + 0, g4.x);
            DSTEP(aa + 1, g4.y);
            DSTEP(aa + 2, g4.z);
            DSTEP(aa + 3, g4.w);
        }
#undef DSTEP
    }

    float* o = out + ((size_t)(b * NN + n0 + ty2) << 9) + m0 + tx4;
    *(float4*)o        = make_float4(a00, a01, a02, a03);
    *(float4*)(o + MM) = make_float4(a10, a11, a12, a13);
}

extern "C" void kernel_launch(void* const* d_in, const int* in_sizes, int n_in,
                              void* d_out, int out_size) {
    const float* data = (const float*)d_in[0];
    const float* crit = (const float*)d_in[1];
    const float* Wl   = (const float*)d_in[2];
    const float* bl   = (const float*)d_in[3];
    const float* Wr   = (const float*)d_in[4];
    const float* br   = (const float*)d_in[5];
    const float* agg  = (const float*)d_in[6];
    float* out = (float*)d_out;

    proj_kernel<<<dim3(32, 4, 2), 256>>>(data, crit, Wl, bl, Wr, br);
    dist_kernel<<<dim3(16, 16, 4), 128>>>(agg, out);
}

// round 9
// speedup vs baseline: 1.0193x; 1.0092x over previous
#include <cuda_runtime.h>
#include <cuda_fp16.h>

#define BB 4
#define NN 512
#define MM 512
#define LD 512
#define AG 256
#define ROWS (BB * NN)   // 2048

__device__ float g_dl[ROWS * AG];   // [row][a]
__device__ float g_cl[ROWS * AG];   // [row][a]

__device__ __forceinline__ float fast_tanh(float x) {
    float y;
    asm("tanh.approx.f32 %0, %1;" : "=f"(y) : "f"(x));
    return y;
}

// Packed 2xFP32 FMA (Blackwell): d = a * b + d, two fp32 lanes per instruction.
__device__ __forceinline__ void ffma2(unsigned long long& d,
                                      unsigned long long a,
                                      unsigned long long b) {
    asm("fma.rn.f32x2 %0, %1, %2, %3;" : "=l"(d) : "l"(a), "l"(b), "l"(d));
}
__device__ __forceinline__ unsigned long long splat2(float x) {
    unsigned long long r;
    asm("mov.b64 %0, {%1, %1};" : "=l"(r) : "f"(x));
    return r;
}
__device__ __forceinline__ float2 unpack2(unsigned long long v) {
    float2 f;
    asm("mov.b64 {%0, %1}, %2;" : "=f"(f.x), "=f"(f.y) : "l"(v));
    return f;
}

// ---------------------------------------------------------------------------
// Projection GEMM: out[row][a] = in[row][:] @ W + bias   (fp32, FFMA2 packed)
// BM=64, BN=64, BK=16, 256 threads, 4x4/thread as 4x2 packed-pair accs,
// double-buffered smem. Per k-step: 8 FFMA2 + 4 splats (vs 16 FFMA scalar).
// ---------------------------------------------------------------------------
__global__ __launch_bounds__(256) void proj_kernel(
    const float* __restrict__ data, const float* __restrict__ crit,
    const float* __restrict__ Wl, const float* __restrict__ bl,
    const float* __restrict__ Wr, const float* __restrict__ br)
{
    __shared__ float As[2][16][68];
    __shared__ float Bs[2][16][68];

    const float* A; const float* W; const float* bias; float* out;
    if (blockIdx.z == 0) { A = data; W = Wl; bias = bl; out = g_dl; }
    else                 { A = crit; W = Wr; bias = br; out = g_cl; }
    const int row0 = blockIdx.x * 64;
    const int col0 = blockIdx.y * 64;

    const int tid = threadIdx.x;
    const int ar  = tid >> 2;
    const int ac  = (tid & 3) << 2;
    const int bro = tid >> 4;
    const int bco = (tid & 15) << 2;
    const int ty  = tid >> 4;
    const int tx  = tid & 15;

    const float* Aptr = A + (row0 + ar) * LD + ac;
    const float* Wptr = W + bro * AG + col0 + bco;

    unsigned long long acc[4][2];
#pragma unroll
    for (int i = 0; i < 4; i++) { acc[i][0] = 0ull; acc[i][1] = 0ull; }

    {
        float4 av = *(const float4*)(Aptr);
        float4 bv = *(const float4*)(Wptr);
        As[0][ac + 0][ar] = av.x;
        As[0][ac + 1][ar] = av.y;
        As[0][ac + 2][ar] = av.z;
        As[0][ac + 3][ar] = av.w;
        *(float4*)&Bs[0][bro][bco] = bv;
    }
    __syncthreads();

    int cur = 0;
    for (int k0 = 0; k0 < LD; k0 += 16) {
        float4 an, bn;
        const bool more = (k0 + 16) < LD;
        if (more) {
            an = *(const float4*)(Aptr + k0 + 16);
            bn = *(const float4*)(Wptr + (size_t)(k0 + 16) * AG);
        }
#pragma unroll
        for (int k = 0; k < 16; k++) {
            float a[4];
            *(float4*)a = *(const float4*)&As[cur][k][ty << 2];
            // b pair-loads: 16B-aligned -> direct 64-bit packed operands
            unsigned long long b01 = *(const unsigned long long*)&Bs[cur][k][tx << 2];
            unsigned long long b23 = *(const unsigned long long*)&Bs[cur][k][(tx << 2) + 2];
#pragma unroll
            for (int i = 0; i < 4; i++) {
                unsigned long long ai = splat2(a[i]);
                ffma2(acc[i][0], ai, b01);
                ffma2(acc[i][1], ai, b23);
            }
        }
        if (more) {
            int nxt = cur ^ 1;
            As[nxt][ac + 0][ar] = an.x;
            As[nxt][ac + 1][ar] = an.y;
            As[nxt][ac + 2][ar] = an.z;
            As[nxt][ac + 3][ar] = an.w;
            *(float4*)&Bs[nxt][bro][bco] = bn;
            __syncthreads();
            cur = nxt;
        }
    }

#pragma unroll
    for (int i = 0; i < 4; i++) {
        int row = row0 + (ty << 2) + i;
        int c   = col0 + (tx << 2);
        float2 p01 = unpack2(acc[i][0]);
        float2 p23 = unpack2(acc[i][1]);
        float4 v;
        v.x = p01.x + bias[c + 0];
        v.y = p01.y + bias[c + 1];
        v.z = p23.x + bias[c + 2];
        v.w = p23.y + bias[c + 3];
        *(float4*)(out + (size_t)row * AG + c) = v;
    }
}

// ---------------------------------------------------------------------------
// Distance kernel: dists[b,n,m] = sum_a tanh(dl[b,n,a] + cl[b,m,a]) * agg[a]
// MUFU-bound at the HW floor (16 tanh/cyc/SM): ~67us. fp32 throughout.
// 32x32 tile / block (grid 1024), 256 threads, 2x2/thread, a chunked by 64.
// ---------------------------------------------------------------------------
__global__ __launch_bounds__(256) void dist_kernel(
    const float* __restrict__ agg, float* __restrict__ out)
{
    __shared__ float dls[64][34];
    __shared__ float cls[64][34];
    __shared__ float aggs[AG];

    const int b  = blockIdx.z;
    const int n0 = blockIdx.x << 5;
    const int m0 = blockIdx.y << 5;
    const int tid = threadIdx.x;
    const int ty2 = (tid >> 4) << 1;   // n rows ty2, ty2+1
    const int tx2 = (tid & 15) << 1;   // m cols tx2, tx2+1

    aggs[tid] = agg[tid];

    const float* dlb = g_dl + (size_t)(b * NN + n0) * AG;
    const float* clb = g_cl + (size_t)(b * MM + m0) * AG;

    float a00 = 0.f, a01 = 0.f, a10 = 0.f, a11 = 0.f;

    for (int a0 = 0; a0 < AG; a0 += 64) {
        __syncthreads();   // protect previous chunk reads (covers aggs on iter 0)
#pragma unroll
        for (int h = 0; h < 2; h++) {
            int idx = tid + (h << 8);       // 0..511
            int r   = idx >> 4;             // 0..31
            int a4  = (idx & 15) << 2;      // 0..60
            float4 v = *(const float4*)(dlb + (size_t)r * AG + a0 + a4);
            dls[a4 + 0][r] = v.x;
            dls[a4 + 1][r] = v.y;
            dls[a4 + 2][r] = v.z;
            dls[a4 + 3][r] = v.w;
            float4 w = *(const float4*)(clb + (size_t)r * AG + a0 + a4);
            cls[a4 + 0][r] = w.x;
            cls[a4 + 1][r] = w.y;
            cls[a4 + 2][r] = w.z;
            cls[a4 + 3][r] = w.w;
        }
        __syncthreads();

#pragma unroll 4
        for (int a = 0; a < 64; a++) {
            float2 d = *(const float2*)&dls[a][ty2];
            float2 c = *(const float2*)&cls[a][tx2];
            float g = aggs[a0 + a];
            a00 = fmaf(fast_tanh(d.x + c.x), g, a00);
            a01 = fmaf(fast_tanh(d.x + c.y), g, a01);
            a10 = fmaf(fast_tanh(d.y + c.x), g, a10);
            a11 = fmaf(fast_tanh(d.y + c.y), g, a11);
        }
    }

    float* o0 = out + ((size_t)(b * NN + n0 + ty2) << 9) + m0 + tx2;
    float* o1 = o0 + MM;
    *(float2*)o0 = make_float2(a00, a01);
    *(float2*)o1 = make_float2(a10, a11);
}

extern "C" void kernel_launch(void* const* d_in, const int* in_sizes, int n_in,
                              void* d_out, int out_size) {
    const float* data = (const float*)d_in[0];
    const float* crit = (const float*)d_in[1];
    const float* Wl   = (const float*)d_in[2];
    const float* bl   = (const float*)d_in[3];
    const float* Wr   = (const float*)d_in[4];
    const float* br   = (const float*)d_in[5];
    const float* agg  = (const float*)d_in[6];
    float* out = (float*)d_out;

    proj_kernel<<<dim3(32, 4, 2), 256>>>(data, crit, Wl, bl, Wr, br);
    dist_kernel<<<dim3(16, 16, 4), 256>>>(agg, out);
}